// round 13
// baseline (speedup 1.0000x reference)
#include <cuda_runtime.h>
#include <cstdint>

#define BATCH   32
#define CIN     64
#define COUT    64
#define HH      64
#define WW      64
#define HOUT    62
#define WOUT    62
#define KTOT    576          // CIN * 3 * 3
#define BLOCK   128
#define KCHUNK  8
#define NCHUNK  72           // 576 / 8
#define WT      68           // w row stride (floats); interleave map col = c + 4*(c>>5)

typedef unsigned long long u64;

// persistent scratch: features transposed to [cin][h][w][batch] (batch contiguous)
__device__ float g_xposed[CIN * HH * WW * BATCH];   // 33.5 MB

__device__ __forceinline__ u64 pk(float lo, float hi) {
    u64 r;
    asm("mov.b64 %0, {%1, %2};" : "=l"(r) : "f"(lo), "f"(hi));
    return r;
}
__device__ __forceinline__ void upk(u64 v, float& lo, float& hi) {
    asm("mov.b64 {%0, %1}, %2;" : "=f"(lo), "=f"(hi) : "l"(v));
}
// Packed dual-FMA on the Blackwell f32x2 pipe (2x FFMA rate)
__device__ __forceinline__ void fma2(u64& d, u64 a, u64 b) {
    asm("fma.rn.f32x2 %0, %1, %2, %0;" : "+l"(d) : "l"(a), "l"(b));
}
__device__ __forceinline__ void cp16(uint32_t dst, const float* src) {
    asm volatile("cp.async.cg.shared.global [%0], [%1], 16;" :: "r"(dst), "l"(src) : "memory");
}
__device__ __forceinline__ void cpcommit() {
    asm volatile("cp.async.commit_group;" ::: "memory");
}
__device__ __forceinline__ void cpwait0() {
    asm volatile("cp.async.wait_group 0;" ::: "memory");
}

// ---------------- kernel 1: transpose features [b][cin][h][w] -> [cin][h][w][b] ----
__global__ void __launch_bounds__(256)
xpose_kernel(const float* __restrict__ features)
{
    __shared__ float t[32][33];
    const int cin = blockIdx.x >> 6;
    const int hh  = blockIdx.x & 63;
    const int ww0 = blockIdx.y << 5;
    const int tx = threadIdx.x & 31;
    const int ty = threadIdx.x >> 5;   // 0..7

    #pragma unroll
    for (int i = 0; i < 4; i++) {
        int b = ty + 8 * i;
        t[b][tx] = features[((b * CIN + cin) * HH + hh) * WW + ww0 + tx];
    }
    __syncthreads();
    #pragma unroll
    for (int i = 0; i < 4; i++) {
        int wwi = ty + 8 * i;
        g_xposed[((cin * HH + hh) * WW + ww0 + wwi) * BATCH + tx] = t[tx][wwi];
    }
}

// ---------------- kernel 2: locally-connected GEMM, 2x2 locations per CTA -----------
// warp = location; thread tile 8 batches x 8 couts (32 FFMA2 per k, 4 L1 wf per k).
__global__ void __launch_bounds__(BLOCK, 4)
lc2d_kernel(const float* __restrict__ weights,
            const float* __restrict__ bias,
            float* __restrict__ out)
{
    __shared__ float x_s[2][4][KCHUNK][BATCH];   // 8 KB   [slot][loc][kk][b]
    __shared__ float w_s[2][4][KCHUNK][WT];      // 17.4 KB [buf][loc][kk][colmap]

    const int tid = threadIdx.x;
    const int wid = tid >> 5;                 // warp = location 0..3
    const int L   = tid & 31;

    const int h0 = blockIdx.y * 2;
    const int w0 = blockIdx.x * 2;
    const int h  = h0 + (wid >> 1);
    const int w  = w0 + (wid & 1);

    // compute mapping: bg -> batches 8bg..8bg+7; cq -> couts 8cq..8cq+7
    const int bg = L & 3;
    const int cq = L >> 2;
    const int c0m = 8 * cq + 4 * (cq >> 2);   // colmap(8cq), contiguous over 8-run

    const float* wloc  = weights + (size_t)(h * WOUT + w) * (COUT * KTOT);
    const float* fbase = g_xposed;

    // w loader (per warp = own location): c in {L, L+32}, two float4 along k
    float4 rel[4];   // [u][v]: c = L + 32u, k-seg v

    auto ldg_w = [&](int ch) {
        #pragma unroll
        for (int u = 0; u < 2; u++)
            #pragma unroll
            for (int v = 0; v < 2; v++)
                rel[u * 2 + v] = *(const float4*)(wloc + (size_t)(L + 32 * u) * KTOT
                                                  + ch * KCHUNK + v * 4);
    };
    // k-major store, interleaved col = c + 4*(c>>5): STS banks (4kk + L + 4u) distinct
    auto sts_w = [&](int buf) {
        #pragma unroll
        for (int u = 0; u < 2; u++) {
            const int col = L + 36 * u;        // colmap(L + 32u)
            #pragma unroll
            for (int v = 0; v < 2; v++) {
                const float* vv = &rel[u * 2 + v].x;
                #pragma unroll
                for (int e = 0; e < 4; e++)
                    w_s[buf][wid][v * 4 + e][col] = vv[e];
            }
        }
    };
    // x gather: 2 coalesced 16B cp.async per thread (all 4 locations)
    auto issue_x = [&](int ch, int slot) {
        #pragma unroll
        for (int s = 0; s < 2; s++) {
            const int idx = tid + s * BLOCK;        // 0..255
            const int l2  = idx >> 6;               // location 0..3
            const int k   = (idx >> 3) & 7;
            const int seg = idx & 7;
            const int r   = ch * KCHUNK + k;
            const int cin = r / 9;
            const int f   = r - cin * 9;
            const int ii  = f / 3;
            const int jj  = f - ii * 3;
            const int row = cin * (HH * WW) + (h0 + (l2 >> 1) + ii) * WW
                          + (w0 + (l2 & 1) + jj);
            const float* src = fbase + (size_t)row * BATCH + seg * 4;
            uint32_t dst = (uint32_t)__cvta_generic_to_shared(&x_s[slot][l2][k][seg * 4]);
            cp16(dst, src);
        }
        cpcommit();
    };

    // ---- prologue ----
    ldg_w(0);
    issue_x(0, 0);
    sts_w(0);
    ldg_w(1);

    u64 acc[4][8];   // [batch-pair bp][cout j]
    #pragma unroll
    for (int p = 0; p < 4; p++)
        #pragma unroll
        for (int j = 0; j < 8; j++) acc[p][j] = 0ULL;

    #pragma unroll 1
    for (int ch = 0; ch < NCHUNK; ch++) {
        cpwait0();            // x(ch) landed
        __syncthreads();      // publish x(ch), w(ch); old slot/buf free

        if (ch + 1 < NCHUNK) {
            sts_w((ch + 1) & 1);
            if (ch + 2 < NCHUNK) ldg_w(ch + 2);
            issue_x(ch + 1, (ch + 1) & 1);     // overlaps with compute below
        }

        const float* xb = &x_s[ch & 1][wid][0][bg * 8];
        const float* wb = &w_s[ch & 1][wid][0][0];

        #pragma unroll
        for (int kk = 0; kk < KCHUNK; kk++) {
            // 8 batches as 4 adjacent pairs: two LDS.128, banks {8bg..}+4s distinct
            ulonglong2 x01 = *(const ulonglong2*)(xb + kk * BATCH);
            ulonglong2 x23 = *(const ulonglong2*)(xb + kk * BATCH + 4);
            // 8 couts: two float4 LDS.128, 16B-groups 2cq+(cq>>2)(+1) mod 8 distinct
            float4 wv0 = *(const float4*)(wb + kk * WT + c0m);
            float4 wv1 = *(const float4*)(wb + kk * WT + c0m + 4);
            u64 wd0 = pk(wv0.x, wv0.x), wd1 = pk(wv0.y, wv0.y);
            u64 wd2 = pk(wv0.z, wv0.z), wd3 = pk(wv0.w, wv0.w);
            u64 wd4 = pk(wv1.x, wv1.x), wd5 = pk(wv1.y, wv1.y);
            u64 wd6 = pk(wv1.z, wv1.z), wd7 = pk(wv1.w, wv1.w);

            fma2(acc[0][0], x01.x, wd0); fma2(acc[1][0], x01.y, wd0);
            fma2(acc[2][0], x23.x, wd0); fma2(acc[3][0], x23.y, wd0);
            fma2(acc[0][1], x01.x, wd1); fma2(acc[1][1], x01.y, wd1);
            fma2(acc[2][1], x23.x, wd1); fma2(acc[3][1], x23.y, wd1);
            fma2(acc[0][2], x01.x, wd2); fma2(acc[1][2], x01.y, wd2);
            fma2(acc[2][2], x23.x, wd2); fma2(acc[3][2], x23.y, wd2);
            fma2(acc[0][3], x01.x, wd3); fma2(acc[1][3], x01.y, wd3);
            fma2(acc[2][3], x23.x, wd3); fma2(acc[3][3], x23.y, wd3);
            fma2(acc[0][4], x01.x, wd4); fma2(acc[1][4], x01.y, wd4);
            fma2(acc[2][4], x23.x, wd4); fma2(acc[3][4], x23.y, wd4);
            fma2(acc[0][5], x01.x, wd5); fma2(acc[1][5], x01.y, wd5);
            fma2(acc[2][5], x23.x, wd5); fma2(acc[3][5], x23.y, wd5);
            fma2(acc[0][6], x01.x, wd6); fma2(acc[1][6], x01.y, wd6);
            fma2(acc[2][6], x23.x, wd6); fma2(acc[3][6], x23.y, wd6);
            fma2(acc[0][7], x01.x, wd7); fma2(acc[1][7], x01.y, wd7);
            fma2(acc[2][7], x23.x, wd7); fma2(acc[3][7], x23.y, wd7);
        }
    }

    // ---- epilogue: unpack batch-pairs, add bias, scattered STG.32 ----
    const float* bl = bias + (h * WOUT + w) * COUT + cq * 8;

    #pragma unroll
    for (int p = 0; p < 4; p++) {
        const int b0 = bg * 8 + 2 * p;
        #pragma unroll
        for (int j = 0; j < 8; j++) {
            const int c = cq * 8 + j;
            float lo, hi;
            upk(acc[p][j], lo, hi);
            const float bv = bl[j];
            out[(((b0    ) * COUT + c) * HOUT + h) * WOUT + w] = lo + bv;
            out[(((b0 + 1) * COUT + c) * HOUT + h) * WOUT + w] = hi + bv;
        }
    }
}

extern "C" void kernel_launch(void* const* d_in, const int* in_sizes, int n_in,
                              void* d_out, int out_size)
{
    const float* features = nullptr;
    const float* weights  = nullptr;
    const float* bias     = nullptr;
    for (int i = 0; i < n_in; i++) {
        if      (in_sizes[i] == BATCH * CIN * HH * WW)        features = (const float*)d_in[i];
        else if (in_sizes[i] == HOUT * WOUT * COUT * CIN * 9) weights  = (const float*)d_in[i];
        else if (in_sizes[i] == HOUT * WOUT * COUT)           bias     = (const float*)d_in[i];
    }
    float* out = (float*)d_out;

    // 1) transpose features -> [cin][h][w][batch]
    xpose_kernel<<<dim3(CIN * HH, WW / 32), 256>>>(features);
    // 2) main locally-connected GEMM (2x2 locations per CTA, warp = location)
    lc2d_kernel<<<dim3(WOUT / 2, HOUT / 2), BLOCK>>>(weights, bias, out);
}

// round 17
// speedup vs baseline: 1.1226x; 1.1226x over previous
#include <cuda_runtime.h>
#include <cstdint>

#define BATCH   32
#define CIN     64
#define COUT    64
#define HH      64
#define WW      64
#define HOUT    62
#define WOUT    62
#define KTOT    576
#define KC      64           // k per chunk
#define NCH     9            // 576 / 64
#define THREADS 128

typedef unsigned long long u64;

// persistent scratch: features transposed to [cin][h][w][batch] (batch contiguous)
__device__ float g_xposed[CIN * HH * WW * BATCH];   // 33.5 MB

// ---- dynamic smem layout (bytes) ----
// W tiles: [buf][hi(64 rows) | lo(64 rows)] rows of 64 bf16 padded to 144 B
#define W_ROW      144
#define W_HALF     (64 * W_ROW)          // 9216  (hi block or lo block)
#define W_BUF      (2 * W_HALF)          // 18432 per buffer
#define SM_X       (2 * W_BUF)           // 36864
// X tiles: [buf] 64 k-rows of 32 fp32 padded to 144 B (36 words)
#define X_ROW_W    36
#define X_BUF      (64 * 144)            // 9216 per buffer
#define SMEM_TOTAL (SM_X + 2 * X_BUF)    // 55296

__device__ __forceinline__ uint32_t smem_u32(const void* p) {
    return (uint32_t)__cvta_generic_to_shared(p);
}
// pack two fp32 -> bf16x2; low half = f_even
__device__ __forceinline__ uint32_t pack2(float f_even, float f_odd) {
    uint32_t r;
    asm("cvt.rn.bf16x2.f32 %0, %1, %2;" : "=r"(r) : "f"(f_odd), "f"(f_even));
    return r;
}
__device__ __forceinline__ void cp16(uint32_t dst, const float* src) {
    asm volatile("cp.async.cg.shared.global [%0], [%1], 16;" :: "r"(dst), "l"(src) : "memory");
}
__device__ __forceinline__ void cpcommit() {
    asm volatile("cp.async.commit_group;" ::: "memory");
}
__device__ __forceinline__ void cpwait0() {
    asm volatile("cp.async.wait_group 0;" ::: "memory");
}
// portable bf16 tensor-core mma (sm_80+ PTX; lowers to HMMA on sm_103a)
__device__ __forceinline__ void mma16816(float* d, const uint32_t* a,
                                         uint32_t b0, uint32_t b1) {
    asm volatile(
        "mma.sync.aligned.m16n8k16.row.col.f32.bf16.bf16.f32 "
        "{%0,%1,%2,%3}, {%4,%5,%6,%7}, {%8,%9}, {%0,%1,%2,%3};"
        : "+f"(d[0]), "+f"(d[1]), "+f"(d[2]), "+f"(d[3])
        : "r"(a[0]), "r"(a[1]), "r"(a[2]), "r"(a[3]), "r"(b0), "r"(b1));
}

// ---------------- kernel 1: transpose features [b][cin][h][w] -> [cin][h][w][b] ----
__global__ void __launch_bounds__(256)
xpose_kernel(const float* __restrict__ features)
{
    __shared__ float t[32][33];
    const int cin = blockIdx.x >> 6;
    const int hh  = blockIdx.x & 63;
    const int ww0 = blockIdx.y << 5;
    const int tx = threadIdx.x & 31;
    const int ty = threadIdx.x >> 5;

    #pragma unroll
    for (int i = 0; i < 4; i++) {
        int b = ty + 8 * i;
        t[b][tx] = features[((b * CIN + cin) * HH + hh) * WW + ww0 + tx];
    }
    __syncthreads();
    #pragma unroll
    for (int i = 0; i < 4; i++) {
        int wwi = ty + 8 * i;
        g_xposed[((cin * HH + hh) * WW + ww0 + wwi) * BATCH + tx] = t[tx][wwi];
    }
}

// ---------------- kernel 2: bf16-split mma.sync GEMM, 1 location per CTA -------------
// D = Wh*Xh + Wl*Xh + Wh*Xl  (Al*Bl term ~2^-16, negligible vs 1e-3 threshold).
// Warp w computes cout rows 16w..16w+15 x all 32 batches.
__global__ void __launch_bounds__(THREADS, 4)
lc2d_kernel(const float* __restrict__ weights,
            const float* __restrict__ bias,
            float* __restrict__ out)
{
    extern __shared__ char smem[];
    char*  Wb = smem;                       // [buf][hi|lo][64 c][144 B]
    float* Xb = (float*)(smem + SM_X);      // [buf][64 k][36 words]

    const int tid  = threadIdx.x;
    const int wid  = tid >> 5;
    const int lane = tid & 31;
    const int g    = lane >> 2;             // group id 0..7
    const int t    = lane & 3;              // thread-in-group 0..3
    const int w = blockIdx.x;
    const int h = blockIdx.y;

    const float* wloc = weights + (size_t)(h * WOUT + w) * (COUT * KTOT);

    // ---- W loader: thread = (c = tid&63, half = tid>>6) holds 32 contiguous k ----
    float4 rel[8];
    auto ldg_w = [&](int ch) {
        const float* src = wloc + (size_t)(tid & 63) * KTOT + ch * KC + (tid >> 6) * 32;
        #pragma unroll
        for (int i = 0; i < 8; i++)
            rel[i] = *(const float4*)(src + i * 4);
    };
    auto sts_w = [&](int buf) {
        const int c    = tid & 63;
        const int half = tid >> 6;
        char* wh = Wb + buf * W_BUF + c * W_ROW + half * 64;
        char* wl = wh + W_HALF;
        const float* f = &rel[0].x;
        #pragma unroll
        for (int u = 0; u < 4; u++) {
            float f0 = f[8*u+0], f1 = f[8*u+1], f2 = f[8*u+2], f3 = f[8*u+3];
            float f4 = f[8*u+4], f5 = f[8*u+5], f6 = f[8*u+6], f7 = f[8*u+7];
            uint32_t h0 = pack2(f0, f1), h1 = pack2(f2, f3);
            uint32_t h2 = pack2(f4, f5), h3 = pack2(f6, f7);
            uint32_t l0 = pack2(f0 - __uint_as_float(h0 << 16),
                                f1 - __uint_as_float(h0 & 0xFFFF0000u));
            uint32_t l1 = pack2(f2 - __uint_as_float(h1 << 16),
                                f3 - __uint_as_float(h1 & 0xFFFF0000u));
            uint32_t l2 = pack2(f4 - __uint_as_float(h2 << 16),
                                f5 - __uint_as_float(h2 & 0xFFFF0000u));
            uint32_t l3 = pack2(f6 - __uint_as_float(h3 << 16),
                                f7 - __uint_as_float(h3 & 0xFFFF0000u));
            *(uint4*)(wh + u * 16) = make_uint4(h0, h1, h2, h3);
            *(uint4*)(wl + u * 16) = make_uint4(l0, l1, l2, l3);
        }
    };
    // ---- X loader: fp32, k-row = 32 contiguous batches; 4x cp.async 16B ----
    auto issue_x = [&](int ch, int slot) {
        #pragma unroll
        for (int s = 0; s < 4; s++) {
            const int idx = tid + s * THREADS;      // 0..511
            const int k   = idx >> 3;
            const int seg = idx & 7;
            const int r   = ch * KC + k;
            const int cin = r / 9;
            const int f   = r - cin * 9;
            const int ii  = f / 3;
            const int jj  = f - ii * 3;
            const float* src = g_xposed
                + ((size_t)cin * (HH * WW) + (h + ii) * WW + (w + jj)) * BATCH + seg * 4;
            uint32_t dst = smem_u32(smem) + SM_X + slot * X_BUF + k * 144 + seg * 16;
            cp16(dst, src);
        }
        cpcommit();
    };

    // ---- prologue ----
    ldg_w(0);
    issue_x(0, 0);
    sts_w(0);
    ldg_w(1);

    float acc[4][4];   // [n-tile][frag reg]
    #pragma unroll
    for (int nt = 0; nt < 4; nt++)
        #pragma unroll
        for (int j = 0; j < 4; j++) acc[nt][j] = 0.0f;

    #pragma unroll 1
    for (int ch = 0; ch < NCH; ch++) {
        cpwait0();            // X(ch) landed
        __syncthreads();      // X(ch)+W(ch) published; other buf free

        if (ch + 1 < NCH) {
            sts_w((ch + 1) & 1);
            if (ch + 2 < NCH) ldg_w(ch + 2);
            issue_x(ch + 1, (ch + 1) & 1);     // overlaps with mma below
        }

        const int buf = ch & 1;
        const char*  Whp = Wb + buf * W_BUF + (wid * 16) * W_ROW;
        const char*  Wlp = Whp + W_HALF;
        const float* Xp  = (const float*)(smem + SM_X + buf * X_BUF);

        #pragma unroll
        for (int ks = 0; ks < 4; ks++) {
            const int k0 = ks * 16;
            const int ao = g * W_ROW + (k0 + 2 * t) * 2;
            uint32_t ah[4], al[4];
            ah[0] = *(const uint32_t*)(Whp + ao);
            ah[1] = *(const uint32_t*)(Whp + ao + 8 * W_ROW);
            ah[2] = *(const uint32_t*)(Whp + ao + 16);
            ah[3] = *(const uint32_t*)(Whp + ao + 8 * W_ROW + 16);
            al[0] = *(const uint32_t*)(Wlp + ao);
            al[1] = *(const uint32_t*)(Wlp + ao + 8 * W_ROW);
            al[2] = *(const uint32_t*)(Wlp + ao + 16);
            al[3] = *(const uint32_t*)(Wlp + ao + 8 * W_ROW + 16);

            const float* xc = Xp + (k0 + 2 * t) * X_ROW_W + g;
            #pragma unroll
            for (int nt = 0; nt < 4; nt++) {
                const float* xn = xc + nt * 8;
                float x0 = xn[0];
                float x1 = xn[X_ROW_W];
                float x2 = xn[8 * X_ROW_W];
                float x3 = xn[9 * X_ROW_W];
                uint32_t bh0 = pack2(x0, x1);
                uint32_t bh1 = pack2(x2, x3);
                uint32_t bl0 = pack2(x0 - __uint_as_float(bh0 << 16),
                                     x1 - __uint_as_float(bh0 & 0xFFFF0000u));
                uint32_t bl1 = pack2(x2 - __uint_as_float(bh1 << 16),
                                     x3 - __uint_as_float(bh1 & 0xFFFF0000u));
                mma16816(acc[nt], ah, bh0, bh1);   // Wh * Xh
                mma16816(acc[nt], al, bh0, bh1);   // Wl * Xh
                mma16816(acc[nt], ah, bl0, bl1);   // Wh * Xl
            }
        }
    }

    // ---- epilogue: D frag (rows g, g+8 of stripe; cols 2t, 2t+1 of n-tile) ----
    const int c0 = wid * 16 + g;
    const float bv0 = bias[(h * WOUT + w) * COUT + c0];
    const float bv1 = bias[(h * WOUT + w) * COUT + c0 + 8];

    #pragma unroll
    for (int nt = 0; nt < 4; nt++) {
        const int n = nt * 8 + 2 * t;
        out[(( n      * COUT + c0    ) * HOUT + h) * WOUT + w] = acc[nt][0] + bv0;
        out[(((n + 1) * COUT + c0    ) * HOUT + h) * WOUT + w] = acc[nt][1] + bv0;
        out[(( n      * COUT + c0 + 8) * HOUT + h) * WOUT + w] = acc[nt][2] + bv1;
        out[(((n + 1) * COUT + c0 + 8) * HOUT + h) * WOUT + w] = acc[nt][3] + bv1;
    }
}

extern "C" void kernel_launch(void* const* d_in, const int* in_sizes, int n_in,
                              void* d_out, int out_size)
{
    const float* features = nullptr;
    const float* weights  = nullptr;
    const float* bias     = nullptr;
    for (int i = 0; i < n_in; i++) {
        if      (in_sizes[i] == BATCH * CIN * HH * WW)        features = (const float*)d_in[i];
        else if (in_sizes[i] == HOUT * WOUT * COUT * CIN * 9) weights  = (const float*)d_in[i];
        else if (in_sizes[i] == HOUT * WOUT * COUT)           bias     = (const float*)d_in[i];
    }
    float* out = (float*)d_out;

    cudaFuncSetAttribute(lc2d_kernel,
                         cudaFuncAttributeMaxDynamicSharedMemorySize, SMEM_TOTAL);

    // 1) transpose features -> [cin][h][w][batch]
    xpose_kernel<<<dim3(CIN * HH, WW / 32), 256>>>(features);
    // 2) bf16-split tensor-core GEMM (1 location per CTA)
    lc2d_kernel<<<dim3(WOUT, HOUT), THREADS, SMEM_TOTAL>>>(weights, bias, out);
}